// round 8
// baseline (speedup 1.0000x reference)
#include <cuda_runtime.h>
#include <cuda_fp16.h>

#define NN 100000
#define EE 3200000
#define HH 8
#define CC 16
#define HC 128
#define PAD 128
#define LOG2E 1.4426950408889634f

// Scratch (__device__ globals -- no allocation allowed).
// Sentinel node NN: logit -1e30 -> weight 0, features 0.
__device__ __half g_h16[(NN + 1) * HC];   // projected features fp16
__device__ float  g_asrc[(NN + 1) * HH];  // src logits (log2 domain)
__device__ float  g_adst[NN * HH];        // dst logits (log2 domain)
__device__ int    g_deg[NN];              // in-degree (excl. self loop)
__device__ int    g_col[NN * PAD];        // padded CSR (sentinel-padded)

struct alignas(8) H4 { __half2 a, b; };

__device__ __forceinline__ float ex2f(float x) {
    float r; asm("ex2.approx.f32 %0, %1;" : "=f"(r) : "f"(x)); return r;
}

__device__ __forceinline__ void mma16816(float* c, const unsigned* a, const unsigned* b) {
    asm volatile("mma.sync.aligned.m16n8k16.row.col.f32.f16.f16.f32 "
                 "{%0,%1,%2,%3},{%4,%5,%6,%7},{%8,%9},{%0,%1,%2,%3};"
                 : "+f"(c[0]), "+f"(c[1]), "+f"(c[2]), "+f"(c[3])
                 : "r"(a[0]), "r"(a[1]), "r"(a[2]), "r"(a[3]), "r"(b[0]), "r"(b[1]));
}

// ---------------- init: zero degree + sentinel node ----------------
__global__ void k_init(void) {
    int i = blockIdx.x * blockDim.x + threadIdx.x;
    if (i < NN) g_deg[i] = 0;
    if (i < HH) g_asrc[NN * HH + i] = -1e30f;
    if (i < HC / 2) ((__half2*)g_h16)[NN * (HC / 2) + i] = __floats2half2_rn(0.f, 0.f);
}

// ------- GEMM: fp16-split tensor-core MMA (3-pass compensation, fp32-class) -------
// Block: 64 rows x 128 cols, 8 warps (2 x 4), warp tile 32x32, K chunk 32.
#define XS 40   // smem row stride in halves (conflict-free: (r*20+t) mod 32 all-distinct)
__global__ void __launch_bounds__(256) k_gemm(const float* __restrict__ x,
                                              const float* __restrict__ W) {
    __shared__ __half sXhi[64 * XS], sXlo[64 * XS];
    __shared__ __half sWhi[HC * XS], sWlo[HC * XS];

    int tid = threadIdx.x;
    int lane = tid & 31, warp = tid >> 5;
    int g = lane >> 2, t = lane & 3;           // mma group / thread-in-group
    int wm = (warp >> 2) * 32;                 // warp row offset in block
    int wn = (warp & 3) * 32;                  // warp col offset
    int rb = blockIdx.x * 64;

    float acc[2][4][4];
#pragma unroll
    for (int mf = 0; mf < 2; mf++)
#pragma unroll
        for (int nf = 0; nf < 4; nf++)
#pragma unroll
            for (int q = 0; q < 4; q++) acc[mf][nf][q] = 0.f;

    for (int k0 = 0; k0 < 128; k0 += 32) {
        // stage X chunk [64 rows x 32 k] split hi/lo
#pragma unroll
        for (int s = 0; s < 2; s++) {
            int i = tid + s * 256;             // 512 float4 groups
            int row = i >> 3, j4 = i & 7;
            int gr = rb + row;
            float4 v = make_float4(0.f, 0.f, 0.f, 0.f);
            if (gr < NN) v = *(const float4*)&x[gr * 128 + k0 + j4 * 4];
            float f[4] = { v.x, v.y, v.z, v.w };
            __half hi[4], lo[4];
#pragma unroll
            for (int q = 0; q < 4; q++) {
                hi[q] = __float2half_rn(f[q]);
                lo[q] = __float2half_rn(f[q] - __half2float(hi[q]));
            }
            int base = row * XS + j4 * 4;
            *(__half2*)&sXhi[base]     = __halves2half2(hi[0], hi[1]);
            *(__half2*)&sXhi[base + 2] = __halves2half2(hi[2], hi[3]);
            *(__half2*)&sXlo[base]     = __halves2half2(lo[0], lo[1]);
            *(__half2*)&sXlo[base + 2] = __halves2half2(lo[2], lo[3]);
        }
        // stage W chunk transposed: sW*[n][k], split hi/lo
#pragma unroll
        for (int s = 0; s < 4; s++) {
            int i = tid + s * 256;             // 1024 float4 groups = 32k x 128n
            int kk = i >> 5, n4 = i & 31;
            float4 v = *(const float4*)&W[(k0 + kk) * 128 + n4 * 4];
            float f[4] = { v.x, v.y, v.z, v.w };
#pragma unroll
            for (int q = 0; q < 4; q++) {
                __half hi = __float2half_rn(f[q]);
                __half lo = __float2half_rn(f[q] - __half2float(hi));
                sWhi[(n4 * 4 + q) * XS + kk] = hi;
                sWlo[(n4 * 4 + q) * XS + kk] = lo;
            }
        }
        __syncthreads();

#pragma unroll
        for (int kb = 0; kb < 32; kb += 16) {
            unsigned ahi[2][4], alo[2][4], bhi[4][2], blo[4][2];
#pragma unroll
            for (int mf = 0; mf < 2; mf++) {
                int r0 = (wm + mf * 16 + g) * XS + kb + 2 * t;
                int r1 = r0 + 8 * XS;
                ahi[mf][0] = *(const unsigned*)&sXhi[r0];
                ahi[mf][1] = *(const unsigned*)&sXhi[r1];
                ahi[mf][2] = *(const unsigned*)&sXhi[r0 + 8];
                ahi[mf][3] = *(const unsigned*)&sXhi[r1 + 8];
                alo[mf][0] = *(const unsigned*)&sXlo[r0];
                alo[mf][1] = *(const unsigned*)&sXlo[r1];
                alo[mf][2] = *(const unsigned*)&sXlo[r0 + 8];
                alo[mf][3] = *(const unsigned*)&sXlo[r1 + 8];
            }
#pragma unroll
            for (int nf = 0; nf < 4; nf++) {
                int n0 = (wn + nf * 8 + g) * XS + kb + 2 * t;
                bhi[nf][0] = *(const unsigned*)&sWhi[n0];
                bhi[nf][1] = *(const unsigned*)&sWhi[n0 + 8];
                blo[nf][0] = *(const unsigned*)&sWlo[n0];
                blo[nf][1] = *(const unsigned*)&sWlo[n0 + 8];
            }
#pragma unroll
            for (int mf = 0; mf < 2; mf++)
#pragma unroll
                for (int nf = 0; nf < 4; nf++) {
                    mma16816(acc[mf][nf], ahi[mf], bhi[nf]);
                    mma16816(acc[mf][nf], ahi[mf], blo[nf]);
                    mma16816(acc[mf][nf], alo[mf], bhi[nf]);
                }
        }
        __syncthreads();
    }

    // epilogue: fp16 store
#pragma unroll
    for (int mf = 0; mf < 2; mf++)
#pragma unroll
        for (int nf = 0; nf < 4; nf++) {
            int col = wn + nf * 8 + 2 * t;
            int r0 = rb + wm + mf * 16 + g;
            int r1 = r0 + 8;
            if (r0 < NN)
                *(__half2*)&g_h16[r0 * HC + col] =
                    __floats2half2_rn(acc[mf][nf][0], acc[mf][nf][1]);
            if (r1 < NN)
                *(__half2*)&g_h16[r1 * HC + col] =
                    __floats2half2_rn(acc[mf][nf][2], acc[mf][nf][3]);
        }
}

// ---------------- attention logits from h16 (log2 domain) ----------------
__global__ void k_logits(const float* __restrict__ att_src, const float* __restrict__ att_dst) {
    int tt = blockIdx.x * blockDim.x + threadIdx.x;
    if (tt >= NN * HH) return;
    int n = tt >> 3, hh = tt & 7;
    const H4* hp = (const H4*)(g_h16 + n * HC + hh * CC);
    const float4* as = (const float4*)(att_src + hh * CC);
    const float4* ad = (const float4*)(att_dst + hh * CC);
    float s = 0.f, d = 0.f;
#pragma unroll
    for (int i = 0; i < 4; i++) {
        H4 hv = hp[i];
        float2 f0 = __half22float2(hv.a);
        float2 f1 = __half22float2(hv.b);
        float4 a = as[i], b = ad[i];
        s += f0.x * a.x + f0.y * a.y + f1.x * a.z + f1.y * a.w;
        d += f0.x * b.x + f0.y * b.y + f1.x * b.z + f1.y * b.w;
    }
    g_asrc[tt] = s * LOG2E;
    g_adst[tt] = d * LOG2E;
}

// ---------------- fill padded CSR in one pass ----------------
__global__ void k_fill(const int* __restrict__ ei) {
    int e = blockIdx.x * blockDim.x + threadIdx.x;
    if (e >= EE) return;
    int s = ei[e], d = ei[EE + e];
    int p = atomicAdd(&g_deg[d], 1);
    if (p < PAD) g_col[d * PAD + p] = s;
}

// ---------------- pad each node's list to a multiple of 8 with sentinel ----------------
__global__ void k_pad(void) {
    int i = blockIdx.x * blockDim.x + threadIdx.x;
    if (i >= NN) return;
    int d = g_deg[i]; if (d > PAD) d = PAD;
    int e = (d + 7) & ~7;
    for (int p = d; p < e; p++) g_col[i * PAD + p] = NN;
}

// ------- fused softmax + aggregation: warp/node, fp16 gather, no predication -------
__global__ void __launch_bounds__(256) k_agg(float* __restrict__ out,
                                             const float* __restrict__ bias) {
    int i = (blockIdx.x * blockDim.x + threadIdx.x) >> 5;
    if (i >= NN) return;
    int lane = threadIdx.x & 31;
    int hh = lane >> 2;

    float adv = g_adst[i * 8 + hh];

    // self loop (log2 domain)
    float t = g_asrc[i * 8 + hh] + adv;
    t = fmaxf(t, 0.2f * t);
    float w = ex2f(t);
    float wsum = w;
    H4 hv = *(const H4*)&g_h16[i * HC + lane * 4];
    float2 f0 = __half22float2(hv.a);
    float2 f1 = __half22float2(hv.b);
    float4 acc = make_float4(w * f0.x, w * f0.y, w * f1.x, w * f1.y);

    int deg = g_deg[i]; if (deg > PAD) deg = PAD;
    int degR = (deg + 7) & ~7;
    int beg = i * PAD, end = beg + degR;
    for (int e = beg; e < end; e += 8) {
        int4 ca = *(const int4*)&g_col[e];
        int4 cb = *(const int4*)&g_col[e + 4];
        int sj[8] = { ca.x, ca.y, ca.z, ca.w, cb.x, cb.y, cb.z, cb.w };
        float as8[8];
#pragma unroll
        for (int j = 0; j < 8; j++) as8[j] = g_asrc[sj[j] * 8 + hh];
        H4 hj[8];
#pragma unroll
        for (int j = 0; j < 8; j++) hj[j] = *(const H4*)&g_h16[sj[j] * HC + lane * 4];
#pragma unroll
        for (int j = 0; j < 8; j++) {
            float tj = as8[j] + adv;
            tj = fmaxf(tj, 0.2f * tj);
            float wj = ex2f(tj);
            wsum += wj;
            float2 g0 = __half22float2(hj[j].a);
            float2 g1 = __half22float2(hj[j].b);
            acc.x += wj * g0.x;
            acc.y += wj * g0.y;
            acc.z += wj * g1.x;
            acc.w += wj * g1.y;
        }
    }

    float inv = 1.f / (wsum + 1e-16f);
    float4 bv = *(const float4*)&bias[lane * 4];
    float4 o = make_float4(acc.x * inv + bv.x, acc.y * inv + bv.y,
                           acc.z * inv + bv.z, acc.w * inv + bv.w);
    *(float4*)&out[i * HC + lane * 4] = o;
}

extern "C" void kernel_launch(void* const* d_in, const int* in_sizes, int n_in,
                              void* d_out, int out_size) {
    const float* x    = (const float*)d_in[0];
    const int*   ei   = (const int*)d_in[1];
    const float* W    = (const float*)d_in[2];
    const float* as   = (const float*)d_in[3];
    const float* ad   = (const float*)d_in[4];
    const float* bias = (const float*)d_in[5];
    float* out = (float*)d_out;

    k_init   <<<(NN + 255) / 256, 256>>>();
    k_gemm   <<<(NN + 63) / 64, 256>>>(x, W);
    k_logits <<<(NN * HH + 255) / 256, 256>>>(as, ad);
    k_fill   <<<(EE + 255) / 256, 256>>>(ei);
    k_pad    <<<(NN + 255) / 256, 256>>>();
    k_agg    <<<(NN * 32 + 255) / 256, 256>>>(out, bias);
}

// round 9
// speedup vs baseline: 1.7235x; 1.7235x over previous
#include <cuda_runtime.h>
#include <cuda_fp16.h>

#define NN 100000
#define EE 3200000
#define HH 8
#define CC 16
#define HC 128
#define PAD 128
#define LOG2E 1.4426950408889634f

// Scratch (__device__ globals -- no allocation allowed).
// Sentinel node NN: logit -1e30 -> weight 0, features 0.
__device__ __half g_h16[(NN + 1) * HC];   // projected features fp16
__device__ float  g_asrc[(NN + 1) * HH];  // src logits (log2 domain)
__device__ float  g_adst[NN * HH];        // dst logits (log2 domain)
__device__ int    g_deg[NN];              // in-degree (excl. self loop)
__device__ int    g_col[NN * PAD];        // padded CSR (sentinel-padded)

struct alignas(8) H4 { __half2 a, b; };

__device__ __forceinline__ float ex2f(float x) {
    float r; asm("ex2.approx.f32 %0, %1;" : "=f"(r) : "f"(x)); return r;
}

// ---------------- init: zero degree + sentinel node ----------------
__global__ void k_init(void) {
    int i = blockIdx.x * blockDim.x + threadIdx.x;
    if (i < NN) g_deg[i] = 0;
    if (i < HH) g_asrc[NN * HH + i] = -1e30f;
    if (i < HC / 2) ((__half2*)g_h16)[NN * (HC / 2) + i] = __floats2half2_rn(0.f, 0.f);
}

// ------- GEMM (proven R4/R6 shape) + fused logits (log2 domain) -------
__global__ void k_gemm(const float* __restrict__ x, const float* __restrict__ W,
                       const float* __restrict__ att_src, const float* __restrict__ att_dst) {
    __shared__ float sX[32][33];
    __shared__ float sW[32][HC];
    int tid = threadIdx.x;
    int lane = tid & 31;
    int rb = blockIdx.x * 32;
    int c = lane * 4;              // 4 contiguous output cols
    int r = (tid >> 5) * 4;        // 4 rows
    int hh = lane >> 2;            // head of this lane's cols
    float4 acc[4];
#pragma unroll
    for (int rr = 0; rr < 4; rr++) acc[rr] = make_float4(0.f, 0.f, 0.f, 0.f);

    for (int k0 = 0; k0 < 128; k0 += 32) {
        for (int idx = tid; idx < 32 * 32; idx += 256) {
            int i = idx >> 5, j = idx & 31;
            sX[i][j] = x[(rb + i) * 128 + k0 + j];
        }
        for (int idx = tid; idx < 32 * 128; idx += 256) {
            int i = idx >> 7, j = idx & 127;
            sW[i][j] = W[(k0 + i) * 128 + j];
        }
        __syncthreads();
#pragma unroll
        for (int kk = 0; kk < 32; kk++) {
            float4 wv = *(const float4*)&sW[kk][c];
#pragma unroll
            for (int rr = 0; rr < 4; rr++) {
                float xv = sX[r + rr][kk];
                acc[rr].x += xv * wv.x;
                acc[rr].y += xv * wv.y;
                acc[rr].z += xv * wv.z;
                acc[rr].w += xv * wv.w;
            }
        }
        __syncthreads();
    }

    // store fp16 features
#pragma unroll
    for (int rr = 0; rr < 4; rr++) {
        H4 hv;
        hv.a = __floats2half2_rn(acc[rr].x, acc[rr].y);
        hv.b = __floats2half2_rn(acc[rr].z, acc[rr].w);
        *(H4*)&g_h16[(rb + r + rr) * HC + c] = hv;
    }

    // fused attention logits; store in log2 domain
    float4 av = *(const float4*)&att_src[hh * CC + (c & 15)];
    float4 dv = *(const float4*)&att_dst[hh * CC + (c & 15)];
#pragma unroll
    for (int rr = 0; rr < 4; rr++) {
        float s = acc[rr].x * av.x + acc[rr].y * av.y + acc[rr].z * av.z + acc[rr].w * av.w;
        float d = acc[rr].x * dv.x + acc[rr].y * dv.y + acc[rr].z * dv.z + acc[rr].w * dv.w;
        s += __shfl_xor_sync(0xffffffffu, s, 1);
        s += __shfl_xor_sync(0xffffffffu, s, 2);
        d += __shfl_xor_sync(0xffffffffu, d, 1);
        d += __shfl_xor_sync(0xffffffffu, d, 2);
        if ((lane & 3) == 0) {
            g_asrc[(rb + r + rr) * 8 + hh] = s * LOG2E;
            g_adst[(rb + r + rr) * 8 + hh] = d * LOG2E;
        }
    }
}

// ---------------- fill padded CSR in one pass ----------------
__global__ void k_fill(const int* __restrict__ ei) {
    int e = blockIdx.x * blockDim.x + threadIdx.x;
    if (e >= EE) return;
    int s = ei[e], d = ei[EE + e];
    int p = atomicAdd(&g_deg[d], 1);
    if (p < PAD) g_col[d * PAD + p] = s;
}

// ---------------- pad each node's list to a multiple of 8 with sentinel ----------------
__global__ void k_pad(void) {
    int i = blockIdx.x * blockDim.x + threadIdx.x;
    if (i >= NN) return;
    int d = g_deg[i]; if (d > PAD) d = PAD;
    int e = (d + 7) & ~7;
    for (int p = d; p < e; p++) g_col[i * PAD + p] = NN;
}

// ------- fused softmax + aggregation: warp/node, fp16 gather, no predication -------
__global__ void __launch_bounds__(256) k_agg(float* __restrict__ out,
                                             const float* __restrict__ bias) {
    int i = (blockIdx.x * blockDim.x + threadIdx.x) >> 5;
    if (i >= NN) return;
    int lane = threadIdx.x & 31;
    int hh = lane >> 2;

    float adv = g_adst[i * 8 + hh];

    // self loop (log2 domain)
    float t = g_asrc[i * 8 + hh] + adv;
    t = fmaxf(t, 0.2f * t);
    float w = ex2f(t);
    float wsum = w;
    H4 hv = *(const H4*)&g_h16[i * HC + lane * 4];
    float2 f0 = __half22float2(hv.a);
    float2 f1 = __half22float2(hv.b);
    float4 acc = make_float4(w * f0.x, w * f0.y, w * f1.x, w * f1.y);

    int deg = g_deg[i]; if (deg > PAD) deg = PAD;
    int degR = (deg + 7) & ~7;
    int beg = i * PAD, end = beg + degR;
    for (int e = beg; e < end; e += 8) {
        int4 ca = *(const int4*)&g_col[e];
        int4 cb = *(const int4*)&g_col[e + 4];
        int sj[8] = { ca.x, ca.y, ca.z, ca.w, cb.x, cb.y, cb.z, cb.w };
        float as8[8];
#pragma unroll
        for (int j = 0; j < 8; j++) as8[j] = g_asrc[sj[j] * 8 + hh];
        H4 hj[8];
#pragma unroll
        for (int j = 0; j < 8; j++) hj[j] = *(const H4*)&g_h16[sj[j] * HC + lane * 4];
#pragma unroll
        for (int j = 0; j < 8; j++) {
            float tj = as8[j] + adv;
            tj = fmaxf(tj, 0.2f * tj);
            float wj = ex2f(tj);
            wsum += wj;
            float2 g0 = __half22float2(hj[j].a);
            float2 g1 = __half22float2(hj[j].b);
            acc.x += wj * g0.x;
            acc.y += wj * g0.y;
            acc.z += wj * g1.x;
            acc.w += wj * g1.y;
        }
    }

    float inv = 1.f / (wsum + 1e-16f);
    float4 bv = *(const float4*)&bias[lane * 4];
    float4 o = make_float4(acc.x * inv + bv.x, acc.y * inv + bv.y,
                           acc.z * inv + bv.z, acc.w * inv + bv.w);
    *(float4*)&out[i * HC + lane * 4] = o;
}

extern "C" void kernel_launch(void* const* d_in, const int* in_sizes, int n_in,
                              void* d_out, int out_size) {
    const float* x    = (const float*)d_in[0];
    const int*   ei   = (const int*)d_in[1];
    const float* W    = (const float*)d_in[2];
    const float* as   = (const float*)d_in[3];
    const float* ad   = (const float*)d_in[4];
    const float* bias = (const float*)d_in[5];
    float* out = (float*)d_out;

    // Fork a side stream so the CSR build (L2-latency-bound, issue ~8%)
    // overlaps the GEMM (FFMA-issue-bound). Standard event fork/join keeps
    // this graph-capturable. Streams/events are host-side objects (no device
    // memory); intentionally not destroyed -- destroying a forked stream
    // before EndCapture would invalidate capture, and kernel_launch only
    // runs a couple of times outside graph replay.
    cudaStream_t s2;
    cudaStreamCreateWithFlags(&s2, cudaStreamNonBlocking);
    cudaEvent_t eFork, eJoin;
    cudaEventCreateWithFlags(&eFork, cudaEventDisableTiming);
    cudaEventCreateWithFlags(&eJoin, cudaEventDisableTiming);

    cudaEventRecord(eFork, 0);
    cudaStreamWaitEvent(s2, eFork, 0);

    // branch A (default stream): dense compute
    k_gemm <<<NN / 32, 256>>>(x, W, as, ad);

    // branch B (s2): CSR build
    k_init <<<(NN + 255) / 256, 256, 0, s2>>>();
    k_fill <<<(EE + 255) / 256, 256, 0, s2>>>(ei);
    k_pad  <<<(NN + 255) / 256, 256, 0, s2>>>();

    cudaEventRecord(eJoin, s2);
    cudaStreamWaitEvent(0, eJoin, 0);

    k_agg  <<<(NN * 32 + 255) / 256, 256>>>(out, bias);
}

// round 10
// speedup vs baseline: 1.9407x; 1.1260x over previous
#include <cuda_runtime.h>
#include <cuda_fp16.h>

#define NN 100000
#define EE 3200000
#define HH 8
#define CC 16
#define HC 128
#define PAD 128
#define LOG2E 1.4426950408889634f

// Scratch (__device__ globals -- no allocation allowed).
// Sentinel node NN: logit -1e30 -> weight 0, features 0.
__device__ __half g_h16[(NN + 1) * HC];   // projected features fp16
__device__ float  g_asrc[(NN + 1) * HH];  // src logits (log2 domain)
__device__ float  g_adst[NN * HH];        // dst logits (log2 domain)
__device__ int    g_deg[NN];              // in-degree (excl. self loop)
__device__ int    g_col[NN * PAD];        // padded CSR (sentinel-padded)

struct alignas(8) H4 { __half2 a, b; };

__device__ __forceinline__ float ex2f(float x) {
    float r; asm("ex2.approx.f32 %0, %1;" : "=f"(r) : "f"(x)); return r;
}

// ---------------- init: zero degree + sentinel node ----------------
__global__ void k_init(void) {
    int i = blockIdx.x * blockDim.x + threadIdx.x;
    if (i < NN) g_deg[i] = 0;
    if (i < HH) g_asrc[NN * HH + i] = -1e30f;
    if (i < HC / 2) ((__half2*)g_h16)[NN * (HC / 2) + i] = __floats2half2_rn(0.f, 0.f);
}

// ------- GEMM: 64-row blocks, 8x4 microtile, k-vectorized LDS.128 loads -------
// Per thread: 8 rows x 4 cols. Per 4 k-steps: 8 broadcast LDS.128 (x) +
// 4 LDS.128 (W) + 128 FFMA  =>  ~9% non-FFMA issue overhead.
__global__ void __launch_bounds__(256) k_gemm(const float* __restrict__ x,
                                              const float* __restrict__ W,
                                              const float* __restrict__ att_src,
                                              const float* __restrict__ att_dst) {
    __shared__ float sX[64][36];    // [row][k], padded row stride (16B-aligned)
    __shared__ float sW[32][HC];
    int tid = threadIdx.x;
    int lane = tid & 31;
    int rb = blockIdx.x * 64;
    int c = lane * 4;               // 4 contiguous output cols
    int r0 = (tid >> 5) * 8;        // 8 rows per thread (warp-uniform)
    int hh = lane >> 2;

    float4 acc[8];
#pragma unroll
    for (int rr = 0; rr < 8; rr++) acc[rr] = make_float4(0.f, 0.f, 0.f, 0.f);

    for (int k0 = 0; k0 < 128; k0 += 32) {
        // stage x chunk [64 rows x 32 k], float4 loads
#pragma unroll
        for (int s = 0; s < 2; s++) {
            int idx = tid + s * 256;        // 512 float4 groups
            int i = idx >> 3, j4 = idx & 7;
            int gr = rb + i;
            float4 v = make_float4(0.f, 0.f, 0.f, 0.f);
            if (gr < NN) v = *(const float4*)&x[gr * 128 + k0 + j4 * 4];
            *(float4*)&sX[i][j4 * 4] = v;
        }
        // stage W chunk [32 k x 128 n]
#pragma unroll
        for (int s = 0; s < 4; s++) {
            int idx = tid + s * 256;        // 1024 float4 groups
            int i = idx >> 5, j4 = idx & 31;
            *(float4*)&sW[i][j4 * 4] = *(const float4*)&W[(k0 + i) * 128 + j4 * 4];
        }
        __syncthreads();

#pragma unroll
        for (int kk0 = 0; kk0 < 32; kk0 += 4) {
            float4 xr[8];
#pragma unroll
            for (int rr = 0; rr < 8; rr++)
                xr[rr] = *(const float4*)&sX[r0 + rr][kk0];   // warp-broadcast
#pragma unroll
            for (int j = 0; j < 4; j++) {
                float4 wv = *(const float4*)&sW[kk0 + j][c];
#pragma unroll
                for (int rr = 0; rr < 8; rr++) {
                    float xv = (j == 0) ? xr[rr].x : (j == 1) ? xr[rr].y
                             : (j == 2) ? xr[rr].z : xr[rr].w;
                    acc[rr].x += xv * wv.x;
                    acc[rr].y += xv * wv.y;
                    acc[rr].z += xv * wv.z;
                    acc[rr].w += xv * wv.w;
                }
            }
        }
        __syncthreads();
    }

    // epilogue: fp16 store + fused log2-domain logits
    float4 av = *(const float4*)&att_src[hh * CC + (c & 15)];
    float4 dv = *(const float4*)&att_dst[hh * CC + (c & 15)];
#pragma unroll
    for (int rr = 0; rr < 8; rr++) {
        int gr = rb + r0 + rr;
        bool ok = (gr < NN);
        if (ok) {
            H4 hv;
            hv.a = __floats2half2_rn(acc[rr].x, acc[rr].y);
            hv.b = __floats2half2_rn(acc[rr].z, acc[rr].w);
            *(H4*)&g_h16[gr * HC + c] = hv;
        }
        float s = acc[rr].x * av.x + acc[rr].y * av.y + acc[rr].z * av.z + acc[rr].w * av.w;
        float d = acc[rr].x * dv.x + acc[rr].y * dv.y + acc[rr].z * dv.z + acc[rr].w * dv.w;
        s += __shfl_xor_sync(0xffffffffu, s, 1);
        s += __shfl_xor_sync(0xffffffffu, s, 2);
        d += __shfl_xor_sync(0xffffffffu, d, 1);
        d += __shfl_xor_sync(0xffffffffu, d, 2);
        if (ok && (lane & 3) == 0) {
            g_asrc[gr * 8 + hh] = s * LOG2E;
            g_adst[gr * 8 + hh] = d * LOG2E;
        }
    }
}

// ---------------- fill padded CSR in one pass ----------------
__global__ void k_fill(const int* __restrict__ ei) {
    int e = blockIdx.x * blockDim.x + threadIdx.x;
    if (e >= EE) return;
    int s = ei[e], d = ei[EE + e];
    int p = atomicAdd(&g_deg[d], 1);
    if (p < PAD) g_col[d * PAD + p] = s;
}

// ---------------- pad each node's list to a multiple of 8 with sentinel ----------------
__global__ void k_pad(void) {
    int i = blockIdx.x * blockDim.x + threadIdx.x;
    if (i >= NN) return;
    int d = g_deg[i]; if (d > PAD) d = PAD;
    int e = (d + 7) & ~7;
    for (int p = d; p < e; p++) g_col[i * PAD + p] = NN;
}

// ------- fused softmax + aggregation: warp/node, fp16 gather, no predication -------
__global__ void __launch_bounds__(256) k_agg(float* __restrict__ out,
                                             const float* __restrict__ bias) {
    int i = (blockIdx.x * blockDim.x + threadIdx.x) >> 5;
    if (i >= NN) return;
    int lane = threadIdx.x & 31;
    int hh = lane >> 2;

    float adv = g_adst[i * 8 + hh];

    // self loop (log2 domain)
    float t = g_asrc[i * 8 + hh] + adv;
    t = fmaxf(t, 0.2f * t);
    float w = ex2f(t);
    float wsum = w;
    H4 hv = *(const H4*)&g_h16[i * HC + lane * 4];
    float2 f0 = __half22float2(hv.a);
    float2 f1 = __half22float2(hv.b);
    float4 acc = make_float4(w * f0.x, w * f0.y, w * f1.x, w * f1.y);

    int deg = g_deg[i]; if (deg > PAD) deg = PAD;
    int degR = (deg + 7) & ~7;
    int beg = i * PAD, end = beg + degR;
    for (int e = beg; e < end; e += 8) {
        int4 ca = *(const int4*)&g_col[e];
        int4 cb = *(const int4*)&g_col[e + 4];
        int sj[8] = { ca.x, ca.y, ca.z, ca.w, cb.x, cb.y, cb.z, cb.w };
        float as8[8];
#pragma unroll
        for (int j = 0; j < 8; j++) as8[j] = g_asrc[sj[j] * 8 + hh];
        H4 hj[8];
#pragma unroll
        for (int j = 0; j < 8; j++) hj[j] = *(const H4*)&g_h16[sj[j] * HC + lane * 4];
#pragma unroll
        for (int j = 0; j < 8; j++) {
            float tj = as8[j] + adv;
            tj = fmaxf(tj, 0.2f * tj);
            float wj = ex2f(tj);
            wsum += wj;
            float2 g0 = __half22float2(hj[j].a);
            float2 g1 = __half22float2(hj[j].b);
            acc.x += wj * g0.x;
            acc.y += wj * g0.y;
            acc.z += wj * g1.x;
            acc.w += wj * g1.y;
        }
    }

    float inv = 1.f / (wsum + 1e-16f);
    float4 bv = *(const float4*)&bias[lane * 4];
    float4 o = make_float4(acc.x * inv + bv.x, acc.y * inv + bv.y,
                           acc.z * inv + bv.z, acc.w * inv + bv.w);
    *(float4*)&out[i * HC + lane * 4] = o;
}

extern "C" void kernel_launch(void* const* d_in, const int* in_sizes, int n_in,
                              void* d_out, int out_size) {
    const float* x    = (const float*)d_in[0];
    const int*   ei   = (const int*)d_in[1];
    const float* W    = (const float*)d_in[2];
    const float* as   = (const float*)d_in[3];
    const float* ad   = (const float*)d_in[4];
    const float* bias = (const float*)d_in[5];
    float* out = (float*)d_out;

    // Fork a side stream: CSR build overlaps the GEMM. Host-side objects only;
    // intentionally not destroyed (capture safety; runs ~2x outside replay).
    cudaStream_t s2;
    cudaStreamCreateWithFlags(&s2, cudaStreamNonBlocking);
    cudaEvent_t eFork, eJoin;
    cudaEventCreateWithFlags(&eFork, cudaEventDisableTiming);
    cudaEventCreateWithFlags(&eJoin, cudaEventDisableTiming);

    cudaEventRecord(eFork, 0);
    cudaStreamWaitEvent(s2, eFork, 0);

    // branch A (default stream): dense compute
    k_gemm <<<(NN + 63) / 64, 256>>>(x, W, as, ad);

    // branch B (s2): CSR build
    k_init <<<(NN + 255) / 256, 256, 0, s2>>>();
    k_fill <<<(EE + 255) / 256, 256, 0, s2>>>(ei);
    k_pad  <<<(NN + 255) / 256, 256, 0, s2>>>();

    cudaEventRecord(eJoin, s2);
    cudaStreamWaitEvent(0, eJoin, 0);

    k_agg  <<<(NN * 32 + 255) / 256, 256>>>(out, bias);
}